// round 16
// baseline (speedup 1.0000x reference)
#include <cuda_runtime.h>
#include <cstdint>
#include <float.h>
#include <math.h>

// Problem constants (fixed by the dataset)
#define TT 64
#define UU 142
#define II 4500
#define BB 16384
#define KK 10

#define NPER 5                 // interleaved: lane owns users v = lane + 32*j
#define FULL_MASK 0xFFFFFFFFu

// Candidate threshold: sims ~ 0.5(s+s^T), triangular(-1,1).
// P(sim>0.35)~0.21 -> ~30 candidates, ~21 rated; P(<10 rated) -> exact fallback.
#define THETA 0.35f

// order-preserving float->uint map; 0 reserved as invalid/consumed sentinel
// (all real keys >= f2ord(0.0f) = 0x80000000 > 0)
__device__ __forceinline__ unsigned f2ord(float f) {
    unsigned b = __float_as_uint(f);
    return (b & 0x80000000u) ? ~b : (b | 0x80000000u);
}
__device__ __forceinline__ unsigned umax5(const unsigned o[NPER]) {
    unsigned a = max(o[0], o[1]);
    unsigned b = max(o[2], o[3]);
    return max(max(a, b), o[4]);
}

__global__ __launch_bounds__(256)
void ucf_kernel(const float* __restrict__ qos,      // (T,U,I)
                const float* __restrict__ uavg,     // (T,U)
                const float* __restrict__ sim,      // (U,U)
                const int*   __restrict__ user_id,  // (B,)
                const int*   __restrict__ item_id,  // (B,)
                const int*   __restrict__ time_id,  // (B,)
                float*       __restrict__ out)      // (B,)
{
    const int warp = (blockIdx.x * blockDim.x + threadIdx.x) >> 5;
    const int lane = threadIdx.x & 31;
    if (warp >= BB) return;

    const int u = __ldg(user_id + warp);
    const int i = __ldg(item_id + warp);
    const int t = __ldg(time_id + warp);

    const float* __restrict__ qbase = qos + (size_t)t * (UU * II) + i;
    const float* __restrict__ srow  = sim + (size_t)u * UU;
    const float* __restrict__ arow  = uavg + (size_t)t * UU;

    // 1) sim row (coalesced 128B LDGs, L2-resident)
    float sv[NPER];
    #pragma unroll
    for (int j = 0; j < NPER; j++) {
        const int v = lane + 32 * j;
        sv[j] = (v < UU) ? __ldg(srow + v) : 0.0f;
    }

    // 2) candidates: sim > THETA; probe qos ONLY for candidates
    unsigned candmask = 0;
    #pragma unroll
    for (int j = 0; j < NPER; j++) {
        const int v = lane + 32 * j;
        if (v < UU && sv[j] > THETA) candmask |= 1u << j;
    }
    float qv[NPER];
    #pragma unroll
    for (int j = 0; j < NPER; j++) {
        const int v = lane + 32 * j;
        qv[j] = ((candmask >> j) & 1u) ? __ldg(qbase + (size_t)v * II) : 0.0f;
    }

    // 3) count rated candidates (one popc + one add-reduce)
    unsigned ratedmask = 0;
    #pragma unroll
    for (int j = 0; j < NPER; j++)
        if (((candmask >> j) & 1u) && qv[j] > 0.0f) ratedmask |= 1u << j;
    const int cnt = __reduce_add_sync(FULL_MASK, __popc(ratedmask));

    // 4) keys: fast path if top-10 provably among rated candidates
    unsigned ordu[NPER];
    if (cnt >= KK) {
        #pragma unroll
        for (int j = 0; j < NPER; j++)
            ordu[j] = ((ratedmask >> j) & 1u) ? f2ord(sv[j]) : 0u;
    } else {
        // rare exact fallback: full masked top-K over all 142
        #pragma unroll
        for (int j = 0; j < NPER; j++) {
            const int v = lane + 32 * j;
            qv[j] = (v < UU) ? __ldg(qbase + (size_t)v * II) : 0.0f;
        }
        #pragma unroll
        for (int j = 0; j < NPER; j++) {
            const int v = lane + 32 * j;
            ordu[j] = (v < UU) ? f2ord(qv[j] > 0.0f ? sv[j] : 0.0f) : 0u;
        }
    }

    // 5) top-K selection: umax5 + ONE REDUX.MAX + ballot per iteration,
    //    fully branch-free winner update (predicated zero of slots equal to
    //    the max on the lowest winning lane). Exact except for exact key
    //    ties, which are measure-zero (fast path) or zero-contribution
    //    (fallback zeros). No BSSY/BSYNC in the loop.
    unsigned selmask = 0;
    #pragma unroll
    for (int k = 0; k < KK; k++) {
        const unsigned best    = umax5(ordu);
        const unsigned maxord  = __reduce_max_sync(FULL_MASK, best);
        const unsigned winners = __ballot_sync(FULL_MASK, best == maxord);
        const bool iswin = (lane == __ffs(winners) - 1);
        #pragma unroll
        for (int j = 0; j < NPER; j++) {
            const bool hit = iswin && (ordu[j] == maxord);
            if (hit) { ordu[j] = 0u; selmask |= 1u << j; }  // predicated SELs
        }
    }

    // 6) epilogue: acc = sum s_k*(r_k-avg_k), Spart = sum s_k; two parallel
    //    5-step shuffle reductions (independent chains pipeline).
    float acc = 0.0f, Sp = 0.0f;
    #pragma unroll
    for (int j = 0; j < NPER; j++) {
        if ((selmask >> j) & 1u) {
            const int v = lane + 32 * j;
            const float s = (qv[j] > 0.0f) ? sv[j] : 0.0f;  // masked weight
            Sp  += s;
            acc += s * (qv[j] - __ldg(arow + v));
        }
    }
    #pragma unroll
    for (int off = 16; off > 0; off >>= 1) {
        acc += __shfl_xor_sync(FULL_MASK, acc, off);
        Sp  += __shfl_xor_sync(FULL_MASK, Sp,  off);
    }

    if (lane == 0)
        out[warp] = __ldg(arow + u) + acc / (Sp + 1e-8f);
}

extern "C" void kernel_launch(void* const* d_in, const int* in_sizes, int n_in,
                              void* d_out, int out_size)
{
    const float* qos   = (const float*)d_in[0];  // (64,142,4500)
    const float* uavg  = (const float*)d_in[1];  // (64,142)
    const float* sim   = (const float*)d_in[2];  // (142,142)
    const int*   uid   = (const int*)  d_in[3];  // (16384,)
    const int*   iid   = (const int*)  d_in[4];  // (16384,)
    const int*   tid   = (const int*)  d_in[5];  // (16384,)
    float*       out   = (float*)d_out;          // (16384,)

    const int threads = 256;                 // verified shape: 1 row/warp
    const int blocks  = (BB * 32) / threads; // 2048
    ucf_kernel<<<blocks, threads>>>(qos, uavg, sim, uid, iid, tid, out);
}

// round 17
// speedup vs baseline: 1.0858x; 1.0858x over previous
#include <cuda_runtime.h>
#include <cstdint>
#include <float.h>
#include <math.h>

// Problem constants (fixed by the dataset)
#define TT 64
#define UU 142
#define II 4500
#define BB 16384
#define KK 10

#define LPR 16                 // lanes per row (half-warp rows)
#define SLOTS 9                // ceil(142/16): lane owns v = (lane&15) + 16*j
#define FULL_MASK 0xFFFFFFFFu

// Candidate threshold: sims ~ 0.5(s+s^T), triangular(-1,1).
// P(sim>0.35)~0.21 -> ~30 candidates, ~21 rated; P(<10 rated) -> exact fallback.
#define THETA 0.35f

// order-preserving float->uint map; 0 reserved as invalid/consumed sentinel
// (all real keys >= f2ord(0.0f) = 0x80000000 > 0)
__device__ __forceinline__ unsigned f2ord(float f) {
    unsigned b = __float_as_uint(f);
    return (b & 0x80000000u) ? ~b : (b | 0x80000000u);
}
__device__ __forceinline__ unsigned umax9(const unsigned o[SLOTS]) {
    unsigned a = max(o[0], o[1]);
    unsigned b = max(o[2], o[3]);
    unsigned c = max(o[4], o[5]);
    unsigned d = max(o[6], o[7]);
    return max(max(max(a, b), max(c, d)), o[8]);
}

__global__ __launch_bounds__(128)
void ucf_kernel(const float* __restrict__ qos,      // (T,U,I)
                const float* __restrict__ uavg,     // (T,U)
                const float* __restrict__ sim,      // (U,U)
                const int*   __restrict__ user_id,  // (B,)
                const int*   __restrict__ item_id,  // (B,)
                const int*   __restrict__ time_id,  // (B,)
                float*       __restrict__ out)      // (B,)
{
    const int gwarp = (blockIdx.x * blockDim.x + threadIdx.x) >> 5;
    const int lane  = threadIdx.x & 31;
    const int half  = lane >> 4;          // 0: row A, 1: row B
    const int hl    = lane & 15;          // lane within half
    const unsigned hmask = 0xFFFFu << (16 * half);

    const int row = 2 * gwarp + half;     // gwarp < 8192 -> row < 16384

    const int u = __ldg(user_id + row);
    const int i = __ldg(item_id + row);
    const int t = __ldg(time_id + row);

    const float* __restrict__ qbase = qos + (size_t)t * (UU * II) + i;
    const float* __restrict__ srow  = sim + (size_t)u * UU;
    const float* __restrict__ arow  = uavg + (size_t)t * UU;

    // 1) sim row (64B per half-warp per slot, L2-resident)
    float sv[SLOTS];
    #pragma unroll
    for (int j = 0; j < SLOTS; j++) {
        const int v = hl + LPR * j;
        sv[j] = (v < UU) ? __ldg(srow + v) : 0.0f;
    }

    // 2) candidates: sim > THETA; probe qos ONLY for candidates
    unsigned candmask = 0;
    #pragma unroll
    for (int j = 0; j < SLOTS; j++) {
        const int v = hl + LPR * j;
        if (v < UU && sv[j] > THETA) candmask |= 1u << j;
    }
    float qv[SLOTS];
    #pragma unroll
    for (int j = 0; j < SLOTS; j++) {
        const int v = hl + LPR * j;
        qv[j] = ((candmask >> j) & 1u) ? __ldg(qbase + (size_t)v * II) : 0.0f;
    }

    // 3) rated-candidate count per half-warp row
    unsigned ratedmask = 0;
    #pragma unroll
    for (int j = 0; j < SLOTS; j++)
        if (((candmask >> j) & 1u) && qv[j] > 0.0f) ratedmask |= 1u << j;
    const int cnt = __reduce_add_sync(hmask, __popc(ratedmask));

    // 4) keys: fast path if top-10 provably among rated candidates
    unsigned ordu[SLOTS];
    if (cnt >= KK) {
        #pragma unroll
        for (int j = 0; j < SLOTS; j++)
            ordu[j] = ((ratedmask >> j) & 1u) ? f2ord(sv[j]) : 0u;
    } else {
        // rare exact fallback: full masked top-K over all 142
        #pragma unroll
        for (int j = 0; j < SLOTS; j++) {
            const int v = hl + LPR * j;
            qv[j] = (v < UU) ? __ldg(qbase + (size_t)v * II) : 0.0f;
        }
        #pragma unroll
        for (int j = 0; j < SLOTS; j++) {
            const int v = hl + LPR * j;
            ordu[j] = (v < UU) ? f2ord(qv[j] > 0.0f ? sv[j] : 0.0f) : 0u;
        }
    }

    // 5) top-K: one umax9 + one REDUX.MAX(half) + one full-warp ballot serves
    //    BOTH rows per iteration (half-warps share the instruction stream).
    //    Winner = lowest lane in the half holding its half's max; branch-free
    //    predicated zeroing. Exact except exact key ties (measure-zero or
    //    zero-contribution), as verified in R15/R16.
    unsigned selmask = 0;
    #pragma unroll
    for (int k = 0; k < KK; k++) {
        const unsigned best    = umax9(ordu);
        const unsigned maxord  = __reduce_max_sync(hmask, best);
        const unsigned winners = __ballot_sync(FULL_MASK, best == maxord);
        const unsigned myw     = (winners >> (16 * half)) & 0xFFFFu;
        const bool iswin = (hl == __ffs(myw) - 1);
        #pragma unroll
        for (int j = 0; j < SLOTS; j++) {
            const bool hit = iswin && (ordu[j] == maxord);
            if (hit) { ordu[j] = 0u; selmask |= 1u << j; }
        }
    }

    // 6) epilogue: acc = sum s_k*(r_k-avg_k), Sp = sum s_k; 4-step half-warp
    //    reductions (xor offsets 8..1 stay within the half).
    float acc = 0.0f, Sp = 0.0f;
    #pragma unroll
    for (int j = 0; j < SLOTS; j++) {
        if ((selmask >> j) & 1u) {
            const int v = hl + LPR * j;
            const float s = (qv[j] > 0.0f) ? sv[j] : 0.0f;  // masked weight
            Sp  += s;
            acc += s * (qv[j] - __ldg(arow + v));
        }
    }
    #pragma unroll
    for (int off = 8; off > 0; off >>= 1) {
        acc += __shfl_xor_sync(FULL_MASK, acc, off);
        Sp  += __shfl_xor_sync(FULL_MASK, Sp,  off);
    }

    if (hl == 0)
        out[row] = __ldg(arow + u) + acc / (Sp + 1e-8f);
}

extern "C" void kernel_launch(void* const* d_in, const int* in_sizes, int n_in,
                              void* d_out, int out_size)
{
    const float* qos   = (const float*)d_in[0];  // (64,142,4500)
    const float* uavg  = (const float*)d_in[1];  // (64,142)
    const float* sim   = (const float*)d_in[2];  // (142,142)
    const int*   uid   = (const int*)  d_in[3];  // (16384,)
    const int*   iid   = (const int*)  d_in[4];  // (16384,)
    const int*   tid   = (const int*)  d_in[5];  // (16384,)
    float*       out   = (float*)d_out;          // (16384,)

    // 8192 warps, 2 rows per warp (one per half-warp)
    const int threads = 128;
    const int blocks  = (BB / 2 * 32) / threads; // 2048
    ucf_kernel<<<blocks, threads>>>(qos, uavg, sim, uid, iid, tid, out);
}